// round 1
// baseline (speedup 1.0000x reference)
#include <cuda_runtime.h>

// NetG: encoder GRU (T=256) -> hidden += noise -> decoder GRU (T=256, input shifted) -> FC head.
// Persistent kernel: weights SMEM-resident, h ping-pong in L2, software grid barrier per step.

#define BSZ 512
#define TSZ 256
#define HSZ 256
#define NBLK 128
#define NTHR 256
#define BT 64   // batch tile per block
#define IT 16   // hidden tile per block

__device__ float g_h[2][HSZ * BSZ];   // [buf][j * BSZ + b]  (hidden-major, batch contiguous)
__device__ unsigned g_count = 0;
__device__ unsigned g_gen = 0;

__device__ __forceinline__ float sigf(float x) {
    return __fdividef(1.0f, 1.0f + __expf(-x));
}
// tanh(x) = 1 - 2/(e^{2x}+1): saturates cleanly to +/-1, no inf/inf NaN.
__device__ __forceinline__ float tanhf_(float x) {
    return 1.0f - __fdividef(2.0f, __expf(2.0f * x) + 1.0f);
}

__device__ __forceinline__ void grid_sync(unsigned nb, unsigned &gen) {
    __syncthreads();
    if (threadIdx.x == 0) {
        unsigned g = gen;
        __threadfence();
        if (atomicAdd(&g_count, 1) == nb - 1) {
            g_count = 0;
            __threadfence();
            atomicExch(&g_gen, g + 1);
        } else {
            while (*(volatile unsigned*)&g_gen != g + 1) { }
        }
        __threadfence();
        gen = g + 1;
    }
    __syncthreads();
}

__device__ __forceinline__ void project_tile(
    const float* __restrict__ h_s, const float* __restrict__ wfc_s,
    float* __restrict__ out, int b0, int iblk, int tid, int tstep,
    float bf0, float bf1, float bf2)
{
    // 128 threads: 4 local batches (one warp each), dot-256 against W_fc rows.
    int bl = iblk * 4 + (tid >> 5);
    int lane = tid & 31;
    float a0 = 0.f, a1 = 0.f, a2 = 0.f;
    #pragma unroll
    for (int k = 0; k < 8; ++k) {
        int j = lane + k * 32;
        float hv = h_s[j * 68 + bl];
        a0 = fmaf(hv, wfc_s[j],       a0);
        a1 = fmaf(hv, wfc_s[256 + j], a1);
        a2 = fmaf(hv, wfc_s[512 + j], a2);
    }
    #pragma unroll
    for (int o = 16; o > 0; o >>= 1) {
        a0 += __shfl_xor_sync(0xffffffffu, a0, o);
        a1 += __shfl_xor_sync(0xffffffffu, a1, o);
        a2 += __shfl_xor_sync(0xffffffffu, a2, o);
    }
    if (lane == 0) {
        int base = ((b0 + bl) * TSZ + tstep) * 3;
        out[base + 0] = a0 + bf0;
        out[base + 1] = a1 + bf1;
        out[base + 2] = a2 + bf2;
    }
}

extern "C" __global__ void __launch_bounds__(NTHR, 1)
netg_kernel(const float* __restrict__ X_p, const float* __restrict__ X_f,
            const float* __restrict__ noise,
            const float* __restrict__ Wih_e, const float* __restrict__ Whh_e,
            const float* __restrict__ bih_e, const float* __restrict__ bhh_e,
            const float* __restrict__ Wih_d, const float* __restrict__ Whh_d,
            const float* __restrict__ bih_d, const float* __restrict__ bhh_d,
            const float* __restrict__ Wfc,   const float* __restrict__ bfc,
            float* __restrict__ out)
{
    extern __shared__ float smem[];
    float* h_s   = smem;                   // 256*68 floats (padded h tile, [j][b_local])
    float* we_s  = h_s + 256 * 68;         // 256*16*4 floats: [j][i_local][r,z,n,pad]
    float* wd_s  = we_s + 256 * 64;
    float* wfc_s = wd_s + 256 * 64;        // 768
    float* x_s   = wfc_s + 768;            // 64*3
    float4* h_s4 = (float4*)h_s;

    const int tid  = threadIdx.x;
    const int iblk = blockIdx.x & 15;      // 16 hidden-tile blocks
    const int bblk = blockIdx.x >> 4;      // 8 batch-tile blocks
    const int b0   = bblk * BT;
    const int bgrp = tid & 15;             // 16 batch groups of 4
    const int il   = tid >> 4;             // 16 local hidden idx
    const int ig   = iblk * IT + il;       // global hidden idx of this thread

    // ---- stage recurrent weight slices (both GRUs) into SMEM, packed [j][i][g] ----
    for (int p = 0; p < 2; ++p) {
        const float* W = p ? Whh_d : Whh_e;
        float* ws = p ? wd_s : we_s;
        #pragma unroll
        for (int k = 0; k < 16; ++k) {
            int idx = tid + k * 256;
            int i2 = idx >> 8;
            int j  = idx & 255;
            int gi = iblk * IT + i2;
            float r = W[gi * HSZ + j];
            float z = W[(HSZ + gi) * HSZ + j];
            float n = W[(2 * HSZ + gi) * HSZ + j];
            float* dst = ws + (j * 16 + i2) * 4;
            dst[0] = r; dst[1] = z; dst[2] = n; dst[3] = 0.f;
        }
    }
    for (int k = tid; k < 768; k += NTHR) wfc_s[k] = Wfc[k];

    // ---- per-thread input-gate params (D=3) and biases, both phases ----
    float wE[9], wD[9], biE[3], biD[3], bhE[3], bhD[3];
    #pragma unroll
    for (int g = 0; g < 3; ++g) {
        int row = g * HSZ + ig;
        biE[g] = bih_e[row]; bhE[g] = bhh_e[row];
        biD[g] = bih_d[row]; bhD[g] = bhh_d[row];
        #pragma unroll
        for (int d = 0; d < 3; ++d) {
            wE[g * 3 + d] = Wih_e[row * 3 + d];
            wD[g * 3 + d] = Wih_d[row * 3 + d];
        }
    }
    const float bf0 = bfc[0], bf1 = bfc[1], bf2 = bfc[2];

    // ---- zero h buffer 0 (encoder h0 = 0); must be redone every launch ----
    {
        float* z = &g_h[0][blockIdx.x * 1024];
        z[tid] = 0.f; z[tid + 256] = 0.f; z[tid + 512] = 0.f; z[tid + 768] = 0.f;
    }

    unsigned gen = *(volatile unsigned*)&g_gen;
    grid_sync(gridDim.x, gen);

    int cur = 0;
    for (int t = 0; t < 2 * TSZ; ++t) {
        const bool enc = (t < TSZ);
        const int tt = enc ? t : t - TSZ;

        // stage x_t tile (decoder input is right-shifted X_f; step 0 -> zeros)
        if (tid < 192) {
            int bl = tid / 3, d = tid - bl * 3;
            float v = 0.f;
            if (enc)          v = X_p[(b0 + bl) * (TSZ * 3) + tt * 3 + d];
            else if (tt > 0)  v = X_f[(b0 + bl) * (TSZ * 3) + (tt - 1) * 3 + d];
            x_s[bl * 3 + d] = v;
        }
        // stage h tile: g_h[cur][j][b0..b0+63] -> h_s[j][b_local] (padded rows)
        {
            const float4* src = (const float4*)&g_h[cur][0];
            const int cofs = b0 >> 2;
            #pragma unroll
            for (int k = 0; k < 16; ++k) {
                int idx = tid + k * 256;
                int j = idx >> 4, b4 = idx & 15;
                h_s4[j * 17 + b4] = src[j * (BSZ / 4) + cofs + b4];
            }
        }
        __syncthreads();

        // fused output head: project Y_{tt-1} (== current h_s) during decoder steps
        if (!enc && tt >= 1 && tid < 128)
            project_tile(h_s, wfc_s, out, b0, iblk, tid, tt - 1, bf0, bf1, bf2);

        // select phase params
        const float bh0 = enc ? bhE[0] : bhD[0];
        const float bh1 = enc ? bhE[1] : bhD[1];
        const float bh2 = enc ? bhE[2] : bhD[2];
        float wi[9], bi3[3];
        #pragma unroll
        for (int q = 0; q < 9; ++q) wi[q] = enc ? wE[q] : wD[q];
        #pragma unroll
        for (int q = 0; q < 3; ++q) bi3[q] = enc ? biE[q] : biD[q];

        // GEMM: gh[g][b] = b_hh[g] + sum_j h[b,j] * W_hh[g,j], 4 batches x 3 gates
        float acc0[4], acc1[4], acc2[4];
        #pragma unroll
        for (int b = 0; b < 4; ++b) { acc0[b] = bh0; acc1[b] = bh1; acc2[b] = bh2; }
        const float4* hp = h_s4 + bgrp;
        const float4* wp = (const float4*)(enc ? we_s : wd_s) + il;
        #pragma unroll 8
        for (int j = 0; j < HSZ; ++j) {
            const float4 hv = hp[j * 17];
            const float4 wv = wp[j * 16];
            acc0[0] = fmaf(wv.x, hv.x, acc0[0]);
            acc0[1] = fmaf(wv.x, hv.y, acc0[1]);
            acc0[2] = fmaf(wv.x, hv.z, acc0[2]);
            acc0[3] = fmaf(wv.x, hv.w, acc0[3]);
            acc1[0] = fmaf(wv.y, hv.x, acc1[0]);
            acc1[1] = fmaf(wv.y, hv.y, acc1[1]);
            acc1[2] = fmaf(wv.y, hv.z, acc1[2]);
            acc1[3] = fmaf(wv.y, hv.w, acc1[3]);
            acc2[0] = fmaf(wv.z, hv.x, acc2[0]);
            acc2[1] = fmaf(wv.z, hv.y, acc2[1]);
            acc2[2] = fmaf(wv.z, hv.z, acc2[2]);
            acc2[3] = fmaf(wv.z, hv.w, acc2[3]);
        }

        // gates + h update (PyTorch GRU: r,z,n order; b_hh_n stays inside r*( ))
        const bool add_noise = enc && (tt == TSZ - 1);
        float hnew[4];
        #pragma unroll
        for (int b = 0; b < 4; ++b) {
            int bl = bgrp * 4 + b;
            float x0 = x_s[bl * 3 + 0], x1 = x_s[bl * 3 + 1], x2 = x_s[bl * 3 + 2];
            float xr = bi3[0] + wi[0] * x0 + wi[1] * x1 + wi[2] * x2;
            float xz = bi3[1] + wi[3] * x0 + wi[4] * x1 + wi[5] * x2;
            float xn = bi3[2] + wi[6] * x0 + wi[7] * x1 + wi[8] * x2;
            float r = sigf(xr + acc0[b]);
            float z = sigf(xz + acc1[b]);
            float n = tanhf_(xn + r * acc2[b]);
            float hprev = h_s[ig * 68 + bl];
            float hn = n + z * (hprev - n);
            if (add_noise) hn += noise[(b0 + bl) * HSZ + ig];
            hnew[b] = hn;
        }
        *(float4*)&g_h[cur ^ 1][ig * BSZ + b0 + bgrp * 4] =
            make_float4(hnew[0], hnew[1], hnew[2], hnew[3]);

        cur ^= 1;
        grid_sync(gridDim.x, gen);
    }

    // epilogue: project the final decoder output Y_{T-1}
    {
        const float4* src = (const float4*)&g_h[cur][0];
        const int cofs = b0 >> 2;
        #pragma unroll
        for (int k = 0; k < 16; ++k) {
            int idx = tid + k * 256;
            int j = idx >> 4, b4 = idx & 15;
            h_s4[j * 17 + b4] = src[j * (BSZ / 4) + cofs + b4];
        }
        __syncthreads();
        if (tid < 128)
            project_tile(h_s, wfc_s, out, b0, iblk, tid, TSZ - 1, bf0, bf1, bf2);
    }
}

extern "C" void kernel_launch(void* const* d_in, const int* in_sizes, int n_in,
                              void* d_out, int out_size) {
    const float* X_p   = (const float*)d_in[0];
    const float* X_f   = (const float*)d_in[1];
    const float* noise = (const float*)d_in[2];
    const float* Wih_e = (const float*)d_in[3];
    const float* Whh_e = (const float*)d_in[4];
    const float* bih_e = (const float*)d_in[5];
    const float* bhh_e = (const float*)d_in[6];
    const float* Wih_d = (const float*)d_in[7];
    const float* Whh_d = (const float*)d_in[8];
    const float* bih_d = (const float*)d_in[9];
    const float* bhh_d = (const float*)d_in[10];
    const float* Wfc   = (const float*)d_in[11];
    const float* bfc   = (const float*)d_in[12];
    float* out = (float*)d_out;

    size_t smem_bytes = (size_t)(256 * 68 + 2 * 256 * 64 + 768 + 192) * sizeof(float);
    cudaFuncSetAttribute(netg_kernel, cudaFuncAttributeMaxDynamicSharedMemorySize,
                         (int)smem_bytes);

    netg_kernel<<<NBLK, NTHR, smem_bytes>>>(
        X_p, X_f, noise, Wih_e, Whh_e, bih_e, bhh_e,
        Wih_d, Whh_d, bih_d, bhh_d, Wfc, bfc, out);
}